// round 2
// baseline (speedup 1.0000x reference)
#include <cuda_runtime.h>
#include <cstdint>
#include <math.h>

// ---------------------------------------------------------------------------
// HierarchicalMoELayer: B=8 S=1024 D_MODEL=512 D_FF=2048, E=64 experts, TOPK=2
// route (count/scan/assign) -> GEMM1(+GELU) -> GEMM2 -> combine
// GEMMs: TF32 mma.sync m16n8k8, cp.async double-buffered 128x128x32 tiles,
//        4 warps of 64x64, cvt.rna on fragments (round-to-nearest accuracy).
// ---------------------------------------------------------------------------

#define kNSUB 8
#define kE    64
#define kT    8192
#define kA    16384     /* assignments = T * TOPK */
#define kDM   512
#define kDF   2048
#define kCAP  1024

#define AS_STR 36       /* A smem row stride (words): %32==4 -> conflict-free */
#define BS_STR 136      /* B smem row stride (words): %32==8 -> conflict-free */
#define SMEM_WORDS (2 * 128 * AS_STR + 2 * 32 * BS_STR)
#define SMEM_BYTES (SMEM_WORDS * 4)

// --------------------------- device scratch (statics) ----------------------
__device__ int   g_cnt[kE];
__device__ int   g_cnt2[kE];
__device__ int   g_off[kE];
__device__ int   g_eid[kA];
__device__ int   g_slot[kA];      // assignment -> compacted row slot
__device__ int   g_rowtok[kA];    // slot -> token
__device__ float g_wa[kA];        // weight * valid per assignment
__device__ float g_h [(size_t)kA * kDF];   // 128 MB GEMM1 output (post-GELU)
__device__ float g_y2[(size_t)kA * kDM];   // 32 MB  GEMM2 output

// ------------------------------- routing -----------------------------------
__global__ void k_zero() {
    int i = threadIdx.x;
    if (i < kE) { g_cnt[i] = 0; g_cnt2[i] = 0; }
}

__global__ void k_count(const int* __restrict__ cat, const int* __restrict__ sub) {
    int a = blockIdx.x * 256 + threadIdx.x;
    if (a < kA) {
        int e = cat[a] * kNSUB + sub[a];
        g_eid[a] = e;
        atomicAdd(&g_cnt[e], 1);
    }
}

__global__ void k_scan() {
    if (threadIdx.x == 0) {
        int s = 0;
        for (int e = 0; e < kE; ++e) { g_off[e] = s; s += g_cnt[e]; }
    }
}

__global__ void k_assign(const float* __restrict__ w) {
    int a = blockIdx.x * 256 + threadIdx.x;
    if (a < kA) {
        int e    = g_eid[a];
        int pos  = atomicAdd(&g_cnt2[e], 1);
        int slot = g_off[e] + pos;
        g_slot[a]      = slot;
        g_rowtok[slot] = a >> 1;                    // token index
        g_wa[a]        = (pos < kCAP) ? w[a] : 0.f; // fold validity into weight
    }
}

// ------------------------------ PTX helpers --------------------------------
__device__ __forceinline__ uint32_t cvt_tf32(uint32_t bits) {
    uint32_t r;
    asm("cvt.rna.tf32.f32 %0, %1;" : "=r"(r) : "f"(__uint_as_float(bits)));
    return r;
}

__device__ __forceinline__ void mma_tf32(float* d, const uint32_t* a, const uint32_t* b) {
    asm volatile(
        "mma.sync.aligned.m16n8k8.row.col.f32.tf32.tf32.f32 "
        "{%0,%1,%2,%3},{%4,%5,%6,%7},{%8,%9},{%0,%1,%2,%3};\n"
        : "+f"(d[0]), "+f"(d[1]), "+f"(d[2]), "+f"(d[3])
        : "r"(a[0]), "r"(a[1]), "r"(a[2]), "r"(a[3]),
          "r"(b[0]), "r"(b[1]));
}

__device__ __forceinline__ void cp_async16(uint32_t dst_smem, const void* src) {
    asm volatile("cp.async.cg.shared.global [%0], [%1], 16;\n"
                 :: "r"(dst_smem), "l"(src));
}
__device__ __forceinline__ void cp_commit() {
    asm volatile("cp.async.commit_group;\n");
}
__device__ __forceinline__ void cp_wait0() {
    asm volatile("cp.async.wait_group 0;\n");
}

// ------------------------------- grouped GEMM ------------------------------
// MODE 0: A = gathered hidden rows, Out = g_h, apply bias+GELU (erf)
// MODE 1: A = g_h (contiguous compacted rows), Out = g_y2, apply bias only
// Tile: BM=128, BN=128, BK=32; 128 threads = 4 warps (2m x 2n), warp 64x64.
template<int KTOT, int NTOT, int MODE>
__global__ void __launch_bounds__(128, 2)
k_gemm(const float* __restrict__ Xin,
       const float* __restrict__ Wt,
       const float* __restrict__ bias)
{
    extern __shared__ uint32_t smem[];
    uint32_t* Asm = smem;                       // [2][128][AS_STR] raw fp32 bits
    uint32_t* Bsm = smem + 2 * 128 * AS_STR;    // [2][32][BS_STR]

    const int e    = blockIdx.z;
    const int cnt  = g_cnt[e];
    const int row0 = blockIdx.y * 128;
    if (row0 >= cnt) return;

    const int off  = g_off[e];
    const int n0   = blockIdx.x * 128;
    const int tid  = threadIdx.x;
    const int lane = tid & 31;
    const int wid  = tid >> 5;
    const int wm   = wid & 1;       // warp row (2), 64 rows each
    const int wn   = wid >> 1;      // warp col (2), 64 cols each
    const int gq   = lane >> 2;     // 0..7
    const int tq   = lane & 3;      // 0..3

    const float* __restrict__ Asrc = (MODE == 0) ? Xin : g_h;
    float*       __restrict__ Out  = (MODE == 0) ? g_h : g_y2;

    // Each thread stages one A row (row tid of the 128-row tile).
    // Invalid rows are clamped to a valid source row; their outputs are never
    // written (epilogue guards on cnt), so garbage-free finite data suffices.
    const int grow = row0 + tid;
    size_t abase;
    if (MODE == 0) {
        abase = (size_t)g_rowtok[(grow < cnt) ? (off + grow) : off] * KTOT;
    } else {
        abase = (size_t)(off + ((grow < cnt) ? grow : (cnt - 1))) * KTOT;
    }
    const float* aRow  = Asrc + abase;
    const float* wbase = Wt + (size_t)e * KTOT * NTOT + n0;

    const uint32_t asAddr = (uint32_t)__cvta_generic_to_shared(Asm);
    const uint32_t bsAddr = (uint32_t)__cvta_generic_to_shared(Bsm);

    auto load_tile = [&](int kt, int st) {
        // A: 128 rows x 32 floats; thread tid -> row tid, 8 x 16B
        uint32_t ad = asAddr + (uint32_t)(st * 128 * AS_STR + tid * AS_STR) * 4u;
        const float* as = aRow + kt * 32;
#pragma unroll
        for (int c = 0; c < 8; ++c)
            cp_async16(ad + c * 16, as + c * 4);
        // B: 32 rows(k) x 128 floats(n); 1024 chunks of 16B over 128 threads
#pragma unroll
        for (int i = 0; i < 8; ++i) {
            int ch = i * 128 + tid;
            int br = ch >> 5;           // k row 0..31
            int bc = ch & 31;           // 16B chunk 0..31
            uint32_t bd = bsAddr + (uint32_t)((st * 32 + br) * BS_STR + bc * 4) * 4u;
            cp_async16(bd, wbase + (size_t)(kt * 32 + br) * NTOT + bc * 4);
        }
        cp_commit();
    };

    float acc[4][8][4];
#pragma unroll
    for (int mi = 0; mi < 4; ++mi)
#pragma unroll
        for (int ni = 0; ni < 8; ++ni)
#pragma unroll
            for (int q = 0; q < 4; ++q) acc[mi][ni][q] = 0.f;

    constexpr int KT = KTOT / 32;
    load_tile(0, 0);

    for (int kt = 0; kt < KT; ++kt) {
        cp_wait0();
        __syncthreads();   // tile kt ready; all warps done with previous iter

        if (kt + 1 < KT) load_tile(kt + 1, (kt + 1) & 1);

        const int st = kt & 1;
        const uint32_t* A0 = Asm + st * 128 * AS_STR;
        const uint32_t* B0 = Bsm + st * 32 * BS_STR;

#pragma unroll
        for (int kk = 0; kk < 32; kk += 8) {
            uint32_t af[4][4], bf[8][2];
#pragma unroll
            for (int mi = 0; mi < 4; ++mi) {
                int r = wm * 64 + mi * 16 + gq;
                af[mi][0] = cvt_tf32(A0[r * AS_STR + kk + tq]);
                af[mi][1] = cvt_tf32(A0[(r + 8) * AS_STR + kk + tq]);
                af[mi][2] = cvt_tf32(A0[r * AS_STR + kk + tq + 4]);
                af[mi][3] = cvt_tf32(A0[(r + 8) * AS_STR + kk + tq + 4]);
            }
#pragma unroll
            for (int ni = 0; ni < 8; ++ni) {
                int c = wn * 64 + ni * 8 + gq;
                bf[ni][0] = cvt_tf32(B0[(kk + tq) * BS_STR + c]);
                bf[ni][1] = cvt_tf32(B0[(kk + tq + 4) * BS_STR + c]);
            }
#pragma unroll
            for (int mi = 0; mi < 4; ++mi)
#pragma unroll
                for (int ni = 0; ni < 8; ++ni)
                    mma_tf32(acc[mi][ni], af[mi], bf[ni]);
        }
    }

    // ------------------------------ epilogue -------------------------------
    const float* bp = bias + (size_t)e * NTOT;
#pragma unroll
    for (int mi = 0; mi < 4; ++mi) {
#pragma unroll
        for (int rr = 0; rr < 2; ++rr) {
            int lrow = row0 + wm * 64 + mi * 16 + gq + rr * 8;
            if (lrow < cnt) {
                float* op = Out + (size_t)(off + lrow) * NTOT;
#pragma unroll
                for (int ni = 0; ni < 8; ++ni) {
                    int c = n0 + wn * 64 + ni * 8 + tq * 2;
                    float v0 = acc[mi][ni][rr * 2 + 0] + bp[c];
                    float v1 = acc[mi][ni][rr * 2 + 1] + bp[c + 1];
                    if (MODE == 0) {  // exact GELU (erf), approximate=False
                        v0 = 0.5f * v0 * (1.f + erff(v0 * 0.70710678118654752f));
                        v1 = 0.5f * v1 * (1.f + erff(v1 * 0.70710678118654752f));
                    }
                    *reinterpret_cast<float2*>(op + c) = make_float2(v0, v1);
                }
            }
        }
    }
}

// ------------------------------- combine ------------------------------------
// out[t, :] = wa[2t] * y2[slot(2t), :] + wa[2t+1] * y2[slot(2t+1), :]
__global__ void k_combine(float* __restrict__ out) {
    int i = blockIdx.x * 256 + threadIdx.x;   // over T * (DM/4)
    if (i >= kT * (kDM / 4)) return;
    int t  = i >> 7;         // DM/4 = 128
    int d4 = i & 127;
    int a0 = t * 2, a1 = t * 2 + 1;
    float w0 = g_wa[a0], w1 = g_wa[a1];
    const float4 v0 = reinterpret_cast<const float4*>(g_y2 + (size_t)g_slot[a0] * kDM)[d4];
    const float4 v1 = reinterpret_cast<const float4*>(g_y2 + (size_t)g_slot[a1] * kDM)[d4];
    float4 r;
    r.x = w0 * v0.x + w1 * v1.x;
    r.y = w0 * v0.y + w1 * v1.y;
    r.z = w0 * v0.z + w1 * v1.z;
    r.w = w0 * v0.w + w1 * v1.w;
    reinterpret_cast<float4*>(out)[i] = r;
}

// ------------------------------- launch --------------------------------------
extern "C" void kernel_launch(void* const* d_in, const int* in_sizes, int n_in,
                              void* d_out, int out_size) {
    const float* hidden = (const float*)d_in[0];  // [8,1024,512]
    const int*   cat    = (const int*)  d_in[1];  // [8,1024,2]
    const int*   sub    = (const int*)  d_in[2];  // [8,1024,2]
    const float* wts    = (const float*)d_in[3];  // [8,1024,2]
    const float* W1     = (const float*)d_in[4];  // [64,512,2048]
    const float* b1     = (const float*)d_in[5];  // [64,2048]
    const float* W2     = (const float*)d_in[6];  // [64,2048,512]
    const float* b2     = (const float*)d_in[7];  // [64,512]
    float*       out    = (float*)d_out;          // [8,1024,512]

    (void)in_sizes; (void)n_in; (void)out_size;

    // Allow >48KB dynamic smem (idempotent; set on the very first, uncaptured
    // correctness call as well, so capture-time launches inherit it).
    cudaFuncSetAttribute(k_gemm<kDM, kDF, 0>,
                         cudaFuncAttributeMaxDynamicSharedMemorySize, SMEM_BYTES);
    cudaFuncSetAttribute(k_gemm<kDF, kDM, 1>,
                         cudaFuncAttributeMaxDynamicSharedMemorySize, SMEM_BYTES);

    k_zero  <<<1, 64>>>();
    k_count <<<kA / 256, 256>>>(cat, sub);
    k_scan  <<<1, 32>>>();
    k_assign<<<kA / 256, 256>>>(wts);

    // GEMM1: rows x 512 @ 512 x 2048 (+GELU) -> g_h
    dim3 g1(kDF / 128, kCAP / 128, kE);
    k_gemm<kDM, kDF, 0><<<g1, 128, SMEM_BYTES>>>(hidden, W1, b1);

    // GEMM2: rows x 2048 @ 2048 x 512 -> g_y2
    dim3 g2(kDM / 128, kCAP / 128, kE);
    k_gemm<kDF, kDM, 1><<<g2, 128, SMEM_BYTES>>>(nullptr, W2, b2);

    // Combine: per-token weighted sum of its two expert outputs
    int ncomb = kT * (kDM / 4);
    k_combine<<<(ncomb + 255) / 256, 256>>>(out);
}

// round 4
// speedup vs baseline: 1.1312x; 1.1312x over previous
#include <cuda_runtime.h>
#include <cstdint>
#include <math.h>

// ---------------------------------------------------------------------------
// HierarchicalMoELayer: B=8 S=1024 D_MODEL=512 D_FF=2048, E=64 experts, TOPK=2
// route -> GEMM1(+GELU) -> GEMM2 -> combine
// GEMMs: legacy mma.sync m16n8k8 tf32 (sm_100 base target; tcgen05 is
// unavailable: toolchain emits .target sm_100, not sm_100a).
// Tile: BM=128 BN=128 BK=32, 8 warps (2m x 4n), warp tile 64x32,
// double-buffered smem, cvt.rna at STS time, 1 syncthreads per k-tile.
// ---------------------------------------------------------------------------

#define kNSUB 8
#define kE    64
#define kT    8192
#define kA    16384     /* assignments = T * TOPK */
#define kDM   512
#define kDF   2048
#define kCAP  1024

#define AS_STR 36       /* A smem row stride words: %32==4 -> conflict-free LDS */
#define BS_STR 136      /* B smem row stride words: %32==8 -> conflict-free LDS */
#define A_WORDS (128 * AS_STR)
#define B_WORDS (32 * BS_STR)
#define SMEM_WORDS (2 * A_WORDS + 2 * B_WORDS)
#define SMEM_BYTES (SMEM_WORDS * 4)

// --------------------------- device scratch (statics) ----------------------
__device__ int   g_cnt[kE];
__device__ int   g_cnt2[kE];
__device__ int   g_off[kE];
__device__ int   g_eid[kA];
__device__ int   g_slot[kA];      // assignment -> compacted row slot
__device__ int   g_rowtok[kA];    // slot -> token
__device__ float g_wa[kA];        // weight * valid per assignment
__device__ float g_h [(size_t)kA * kDF];   // 128 MB GEMM1 output (post-GELU)
__device__ float g_y2[(size_t)kA * kDM];   // 32 MB  GEMM2 output

// ------------------------------- routing -----------------------------------
__global__ void k_zero() {
    int i = threadIdx.x;
    if (i < kE) { g_cnt[i] = 0; g_cnt2[i] = 0; }
}

__global__ void k_count(const int* __restrict__ cat, const int* __restrict__ sub) {
    int a = blockIdx.x * 256 + threadIdx.x;
    if (a < kA) {
        int e = cat[a] * kNSUB + sub[a];
        g_eid[a] = e;
        atomicAdd(&g_cnt[e], 1);
    }
}

__global__ void k_scan() {
    if (threadIdx.x == 0) {
        int s = 0;
        for (int e = 0; e < kE; ++e) { g_off[e] = s; s += g_cnt[e]; }
    }
}

__global__ void k_assign(const float* __restrict__ w) {
    int a = blockIdx.x * 256 + threadIdx.x;
    if (a < kA) {
        int e    = g_eid[a];
        int pos  = atomicAdd(&g_cnt2[e], 1);
        int slot = g_off[e] + pos;
        g_slot[a]      = slot;
        g_rowtok[slot] = a >> 1;                    // token index
        g_wa[a]        = (pos < kCAP) ? w[a] : 0.f; // fold validity into weight
    }
}

// ------------------------------ TF32 helpers -------------------------------
__device__ __forceinline__ uint32_t f2tf32(float x) {
    uint32_t r;
    asm("cvt.rna.tf32.f32 %0, %1;" : "=r"(r) : "f"(x));
    return r;
}

__device__ __forceinline__ void mma_tf32(float* d, const uint32_t* a, const uint32_t* b) {
    asm volatile(
        "mma.sync.aligned.m16n8k8.row.col.f32.tf32.tf32.f32 "
        "{%0,%1,%2,%3},{%4,%5,%6,%7},{%8,%9},{%0,%1,%2,%3};\n"
        : "+f"(d[0]), "+f"(d[1]), "+f"(d[2]), "+f"(d[3])
        : "r"(a[0]), "r"(a[1]), "r"(a[2]), "r"(a[3]),
          "r"(b[0]), "r"(b[1]));
}

// ------------------------------- grouped GEMM ------------------------------
// MODE 0: A = gathered hidden rows (via g_rowtok), Out = g_h, bias+GELU(erf)
// MODE 1: A = g_h contiguous compacted rows,        Out = g_y2, bias only
// BM=128 BN=128 BK=32; 256 threads = 8 warps (2m x 4n), warp tile 64x32.
template<int KTOT, int NTOT, int MODE>
__global__ void __launch_bounds__(256, 1)
k_gemm(const float* __restrict__ Xin,
       const float* __restrict__ Wt,
       const float* __restrict__ bias)
{
    extern __shared__ uint32_t smem[];
    uint32_t* Abuf = smem;                 // [2][128][AS_STR] tf32 bits
    uint32_t* Bbuf = smem + 2 * A_WORDS;   // [2][32][BS_STR]

    const int e    = blockIdx.z;
    const int cnt  = g_cnt[e];
    const int row0 = blockIdx.y * 128;
    if (row0 >= cnt) return;

    const int off  = g_off[e];
    const int n0   = blockIdx.x * 128;
    const int tid  = threadIdx.x;
    const int lane = tid & 31;
    const int wid  = tid >> 5;
    const int wm   = wid & 1;       // warp row (2): 64 rows
    const int wn   = wid >> 1;      // warp col (4): 32 cols
    const int gq   = lane >> 2;     // 0..7
    const int tq   = lane & 3;      // 0..3

    const float* __restrict__ Asrc = (MODE == 0) ? Xin : g_h;
    float*       __restrict__ Out  = (MODE == 0) ? g_h : g_y2;

    // --- A staging: 4 rows per thread (rows tid>>3 + {0,32,64,96}) ---------
    const int ar  = tid >> 3;    // 0..31
    const int akq = tid & 7;     // float4 index along K within 32
    const float4* aptr[4];
    bool aval[4];
#pragma unroll
    for (int p = 0; p < 4; ++p) {
        int lrow = p * 32 + ar;
        int grow = row0 + lrow;
        bool v = grow < cnt;
        aval[p] = v;
        size_t base = 0;
        if (v) {
            if (MODE == 0) base = (size_t)g_rowtok[off + grow] * KTOT;
            else           base = (size_t)(off + grow) * KTOT;
        }
        aptr[p] = reinterpret_cast<const float4*>(Asrc + base) + akq;
    }
    // --- B staging: 4 float4 per thread (rows tid>>5 + {0,8,16,24}) --------
    const int br  = tid >> 5;    // 0..7
    const int bc  = tid & 31;    // 16B chunk 0..31 within 128-wide row
    const float* wbase = Wt + (size_t)e * KTOT * NTOT + n0;

    float4 stA[4], stB[4];

    auto ldg_tile = [&](int kt) {
#pragma unroll
        for (int p = 0; p < 4; ++p)
            stA[p] = aval[p] ? aptr[p][kt * 8] : make_float4(0.f, 0.f, 0.f, 0.f);
#pragma unroll
        for (int j = 0; j < 4; ++j)
            stB[j] = *reinterpret_cast<const float4*>(
                wbase + (size_t)(kt * 32 + j * 8 + br) * NTOT + bc * 4);
    };
    auto sts_tile = [&](int st) {
        uint32_t* A0 = Abuf + st * A_WORDS;
        uint32_t* B0 = Bbuf + st * B_WORDS;
#pragma unroll
        for (int p = 0; p < 4; ++p) {
            uint4 u;
            u.x = f2tf32(stA[p].x); u.y = f2tf32(stA[p].y);
            u.z = f2tf32(stA[p].z); u.w = f2tf32(stA[p].w);
            *reinterpret_cast<uint4*>(&A0[(p * 32 + ar) * AS_STR + akq * 4]) = u;
        }
#pragma unroll
        for (int j = 0; j < 4; ++j) {
            uint4 u;
            u.x = f2tf32(stB[j].x); u.y = f2tf32(stB[j].y);
            u.z = f2tf32(stB[j].z); u.w = f2tf32(stB[j].w);
            *reinterpret_cast<uint4*>(&B0[(j * 8 + br) * BS_STR + bc * 4]) = u;
        }
    };

    float acc[4][4][4];
#pragma unroll
    for (int mi = 0; mi < 4; ++mi)
#pragma unroll
        for (int ni = 0; ni < 4; ++ni)
#pragma unroll
            for (int q = 0; q < 4; ++q) acc[mi][ni][q] = 0.f;

    constexpr int KT = KTOT / 32;
    ldg_tile(0);
    sts_tile(0);
    __syncthreads();

    for (int kt = 0; kt < KT; ++kt) {
        if (kt + 1 < KT) ldg_tile(kt + 1);   // prefetch next tile into regs

        const uint32_t* A0 = Abuf + (kt & 1) * A_WORDS;
        const uint32_t* B0 = Bbuf + (kt & 1) * B_WORDS;

#pragma unroll
        for (int kk = 0; kk < 32; kk += 8) {
            uint32_t af[4][4], bf[4][2];
#pragma unroll
            for (int mi = 0; mi < 4; ++mi) {
                int r = wm * 64 + mi * 16 + gq;
                af[mi][0] = A0[r * AS_STR + kk + tq];
                af[mi][1] = A0[(r + 8) * AS_STR + kk + tq];
                af[mi][2] = A0[r * AS_STR + kk + tq + 4];
                af[mi][3] = A0[(r + 8) * AS_STR + kk + tq + 4];
            }
#pragma unroll
            for (int ni = 0; ni < 4; ++ni) {
                int c = wn * 32 + ni * 8 + gq;
                bf[ni][0] = B0[(kk + tq) * BS_STR + c];
                bf[ni][1] = B0[(kk + tq + 4) * BS_STR + c];
            }
#pragma unroll
            for (int mi = 0; mi < 4; ++mi)
#pragma unroll
                for (int ni = 0; ni < 4; ++ni)
                    mma_tf32(acc[mi][ni], af[mi], bf[ni]);
        }

        if (kt + 1 < KT) {
            sts_tile((kt + 1) & 1);   // other buffer: no one reads it
            __syncthreads();          // single sync per k-tile
        }
    }

    // ------------------------------ epilogue -------------------------------
    const float* bp = bias + (size_t)e * NTOT;
#pragma unroll
    for (int mi = 0; mi < 4; ++mi) {
#pragma unroll
        for (int rr = 0; rr < 2; ++rr) {
            int lrow = row0 + wm * 64 + mi * 16 + gq + rr * 8;
            if (lrow < cnt) {
                float* op = Out + (size_t)(off + lrow) * NTOT;
#pragma unroll
                for (int ni = 0; ni < 4; ++ni) {
                    int c = n0 + wn * 32 + ni * 8 + tq * 2;
                    float v0 = acc[mi][ni][rr * 2 + 0] + bp[c];
                    float v1 = acc[mi][ni][rr * 2 + 1] + bp[c + 1];
                    if (MODE == 0) {  // exact GELU (erf), approximate=False
                        v0 = 0.5f * v0 * (1.f + erff(v0 * 0.70710678118654752f));
                        v1 = 0.5f * v1 * (1.f + erff(v1 * 0.70710678118654752f));
                    }
                    *reinterpret_cast<float2*>(op + c) = make_float2(v0, v1);
                }
            }
        }
    }
}

// ------------------------------- combine ------------------------------------
// out[t, :] = wa[2t] * y2[slot(2t), :] + wa[2t+1] * y2[slot(2t+1), :]
__global__ void k_combine(float* __restrict__ out) {
    int i = blockIdx.x * 256 + threadIdx.x;   // over T * (DM/4)
    if (i >= kT * (kDM / 4)) return;
    int t  = i >> 7;         // DM/4 = 128
    int d4 = i & 127;
    int a0 = t * 2, a1 = t * 2 + 1;
    float w0 = g_wa[a0], w1 = g_wa[a1];
    const float4 v0 = reinterpret_cast<const float4*>(g_y2 + (size_t)g_slot[a0] * kDM)[d4];
    const float4 v1 = reinterpret_cast<const float4*>(g_y2 + (size_t)g_slot[a1] * kDM)[d4];
    float4 r;
    r.x = w0 * v0.x + w1 * v1.x;
    r.y = w0 * v0.y + w1 * v1.y;
    r.z = w0 * v0.z + w1 * v1.z;
    r.w = w0 * v0.w + w1 * v1.w;
    reinterpret_cast<float4*>(out)[i] = r;
}

// ------------------------------- launch --------------------------------------
extern "C" void kernel_launch(void* const* d_in, const int* in_sizes, int n_in,
                              void* d_out, int out_size) {
    const float* hidden = (const float*)d_in[0];  // [8,1024,512]
    const int*   cat    = (const int*)  d_in[1];  // [8,1024,2]
    const int*   sub    = (const int*)  d_in[2];  // [8,1024,2]
    const float* wts    = (const float*)d_in[3];  // [8,1024,2]
    const float* W1     = (const float*)d_in[4];  // [64,512,2048]
    const float* b1     = (const float*)d_in[5];  // [64,2048]
    const float* W2     = (const float*)d_in[6];  // [64,2048,512]
    const float* b2     = (const float*)d_in[7];  // [64,512]
    float*       out    = (float*)d_out;          // [8,1024,512]

    (void)in_sizes; (void)n_in; (void)out_size;

    cudaFuncSetAttribute(k_gemm<kDM, kDF, 0>,
                         cudaFuncAttributeMaxDynamicSharedMemorySize, SMEM_BYTES);
    cudaFuncSetAttribute(k_gemm<kDF, kDM, 1>,
                         cudaFuncAttributeMaxDynamicSharedMemorySize, SMEM_BYTES);

    k_zero  <<<1, 64>>>();
    k_count <<<kA / 256, 256>>>(cat, sub);
    k_scan  <<<1, 32>>>();
    k_assign<<<kA / 256, 256>>>(wts);

    // GEMM1: rows x 512 @ 512 x 2048 (+GELU) -> g_h
    dim3 g1(kDF / 128, kCAP / 128, kE);
    k_gemm<kDM, kDF, 0><<<g1, 256, SMEM_BYTES>>>(hidden, W1, b1);

    // GEMM2: rows x 2048 @ 2048 x 512 -> g_y2
    dim3 g2(kDM / 128, kCAP / 128, kE);
    k_gemm<kDF, kDM, 1><<<g2, 256, SMEM_BYTES>>>(nullptr, W2, b2);

    // Combine: per-token weighted sum of its two expert outputs
    int ncomb = kT * (kDM / 4);
    k_combine<<<(ncomb + 255) / 256, 256>>>(out);
}